// round 15
// baseline (speedup 1.0000x reference)
#include <cuda_runtime.h>
#include <cuda_bf16.h>
#include <cstdint>
#include <cstddef>
#include <cstring>

#define CIN 32
#define K1  128
#define K2  512
#define FCD 256
#define MAXN 524288
#define MAXB 16

typedef unsigned long long u64;

__device__ float g_att[(size_t)MAXN * K2];
__device__ uint4 g_Ah4[(size_t)MAXN * 16];   // bf16 hi, row-major [p][128]
__device__ uint4 g_Al4[(size_t)MAXN * 16];   // bf16 lo
__device__ uint4 g_Bh4[K2 * 16];             // w2 hi, [n][128]
__device__ uint4 g_Bl4[K2 * 16];
__device__ float g_mom[1088];                // Sxx[32*32] + sums[32]
__device__ float g_s2[2 * K2];
__device__ float g_bn2[2 * K2];
__device__ float g_pooled[MAXB * K2 * CIN];
__device__ float g_resraw[MAXB * FCD];

__device__ __forceinline__ u64 pk2(float lo, float hi) {
    u64 r; asm("mov.b64 %0, {%1, %2};" : "=l"(r) : "f"(lo), "f"(hi)); return r;
}
__device__ __forceinline__ void fma2(u64 &d, u64 a, u64 b) {
    asm("fma.rn.f32x2 %0, %1, %2, %0;" : "+l"(d) : "l"(a), "l"(b));
}
__device__ __forceinline__ float2 upk2(u64 v) {
    float lo, hi; asm("mov.b64 {%0, %1}, %2;" : "=f"(lo), "=f"(hi) : "l"(v));
    return make_float2(lo, hi);
}
__device__ __forceinline__ uint32_t smem_u32(const void* p) {
    uint32_t a;
    asm("{ .reg .u64 t; cvta.to.shared.u64 t, %1; cvt.u32.u64 %0, t; }" : "=r"(a) : "l"(p));
    return a;
}
__device__ __forceinline__ void cpasync16(uint32_t dst, const void* src) {
    asm volatile("cp.async.cg.shared.global [%0], [%1], 16;" :: "r"(dst), "l"(src));
}
#define CP_COMMIT() asm volatile("cp.async.commit_group;" ::: "memory")

__device__ __forceinline__ void ldm4(uint32_t* r, uint32_t a) {
    asm volatile("ldmatrix.sync.aligned.m8n8.x4.shared.b16 {%0,%1,%2,%3}, [%4];"
        : "=r"(r[0]), "=r"(r[1]), "=r"(r[2]), "=r"(r[3]) : "r"(a));
}
__device__ __forceinline__ void ldm4t(uint32_t* r, uint32_t a) {
    asm volatile("ldmatrix.sync.aligned.m8n8.x4.trans.shared.b16 {%0,%1,%2,%3}, [%4];"
        : "=r"(r[0]), "=r"(r[1]), "=r"(r[2]), "=r"(r[3]) : "r"(a));
}
__device__ __forceinline__ void mma16816(float* d, const uint32_t* a, uint32_t b0, uint32_t b1) {
    asm volatile("mma.sync.aligned.m16n8k16.row.col.f32.bf16.bf16.f32 "
        "{%0,%1,%2,%3}, {%4,%5,%6,%7}, {%8,%9}, {%0,%1,%2,%3};"
        : "+f"(d[0]), "+f"(d[1]), "+f"(d[2]), "+f"(d[3])
        : "r"(a[0]), "r"(a[1]), "r"(a[2]), "r"(a[3]), "r"(b0), "r"(b1));
}

__device__ __forceinline__ void split8(const float* v, uint32_t* hw, uint32_t* lw) {
#pragma unroll
    for (int j = 0; j < 4; j++) {
        float f0 = v[2 * j], f1 = v[2 * j + 1];
        __nv_bfloat162 h2 = __floats2bfloat162_rn(f0, f1);
        float r0 = f0 - __low2float(h2);
        float r1 = f1 - __high2float(h2);
        __nv_bfloat162 l2 = __floats2bfloat162_rn(r0, r1);
        memcpy(&hw[j], &h2, 4); memcpy(&lw[j], &l2, 4);
    }
}

// zero + w2 split prep
__global__ void k_zero(float* outp, int B, const float* __restrict__ w2) {
    int i = blockIdx.x * blockDim.x + threadIdx.x;
    if (i < B * K2 * CIN) g_pooled[i] = 0.f;
    if (i < 1088) g_mom[i] = 0.f;
    if (i < 2 * K2) g_s2[i] = 0.f;
    if (i < B * K2) outp[B * FCD + i] = 0.f;
    if (i < K2 * 16) {
        int n = i >> 4, q = i & 15;
        float v[8];
        *(float4*)v       = *(const float4*)(w2 + (size_t)n * 128 + q * 8);
        *(float4*)(v + 4) = *(const float4*)(w2 + (size_t)n * 128 + q * 8 + 4);
        uint32_t hw[4], lw[4];
        split8(v, hw, lw);
        g_Bh4[n * 16 + q] = make_uint4(hw[0], hw[1], hw[2], hw[3]);
        g_Bl4[n * 16 + q] = make_uint4(lw[0], lw[1], lw[2], lw[3]);
    }
}

// x moments
__global__ __launch_bounds__(256) void k_moments(const float* __restrict__ x, int N) {
    __shared__ float xs[128 * 34];
    int tid = threadIdx.x, tt = tid & 31, rep = tid >> 5;
    int i0 = (tt >> 2) * 4, j0 = (tt & 3) * 8;
    int npb = N / gridDim.x;
    size_t base = (size_t)blockIdx.x * npb;
    u64 acc[4][4];
#pragma unroll
    for (int a = 0; a < 4; a++)
#pragma unroll
        for (int q = 0; q < 4; q++) acc[a][q] = 0ull;
    float ssum[4] = {0.f, 0.f, 0.f, 0.f};
    for (int t = 0; t < npb / 128; t++) {
        __syncthreads();
        for (int i = tid; i < 1024; i += 256) {
            int p = i >> 3, q = i & 7;
            float4 v = *(const float4*)&x[(base + t * 128 + p) * CIN + q * 4];
            *(float2*)&xs[p * 34 + q * 4]     = make_float2(v.x, v.y);
            *(float2*)&xs[p * 34 + q * 4 + 2] = make_float2(v.z, v.w);
        }
        __syncthreads();
        for (int pp = 0; pp < 16; pp++) {
            const float* xr = &xs[(rep * 16 + pp) * 34];
            float xi[4]; u64 xj[4];
#pragma unroll
            for (int a = 0; a < 4; a++) xi[a] = xr[i0 + a];
#pragma unroll
            for (int q = 0; q < 4; q++) xj[q] = *(const u64*)&xr[j0 + 2 * q];
#pragma unroll
            for (int a = 0; a < 4; a++) {
                u64 ap = pk2(xi[a], xi[a]);
#pragma unroll
                for (int q = 0; q < 4; q++) fma2(acc[a][q], ap, xj[q]);
            }
            if ((tt & 3) == 0)
#pragma unroll
                for (int a = 0; a < 4; a++) ssum[a] += xi[a];
        }
    }
#pragma unroll
    for (int a = 0; a < 4; a++)
#pragma unroll
        for (int q = 0; q < 4; q++) {
            float2 f = upk2(acc[a][q]);
            atomicAdd(&g_mom[(i0 + a) * 32 + j0 + 2 * q], f.x);
            atomicAdd(&g_mom[(i0 + a) * 32 + j0 + 2 * q + 1], f.y);
        }
    if ((tt & 3) == 0)
#pragma unroll
        for (int a = 0; a < 4; a++) atomicAdd(&g_mom[1024 + i0 + a], ssum[a]);
}

// fused GEMM1 + analytic BN1 + relu + bf16 hi/lo split -> A images
__global__ __launch_bounds__(256) void k_gemm1f(const float* __restrict__ x,
                                                const float* __restrict__ w1,
                                                const float* __restrict__ b1,
                                                const float* __restrict__ g1,
                                                const float* __restrict__ be1,
                                                float invN, int N) {
    __shared__ __align__(16) float w1s[K1 * CIN];
    __shared__ float cf[3 * K1];
    __shared__ uint32_t sh_hi[256 * 17];
    __shared__ uint32_t sh_lo[256 * 17];
    int tid = threadIdx.x, lane = tid & 31, w = tid >> 5;
    for (int i = tid; i < K1 * CIN; i += 256) w1s[i] = w1[i];
    if (tid < K1) cf[2 * K1 + tid] = b1[tid];
    size_t p0 = (size_t)blockIdx.x * 256;
    u64 xp2[16];
    const float4* xp = (const float4*)(x + (p0 + tid) * CIN);
#pragma unroll
    for (int q = 0; q < 8; q++) {
        float4 v = xp[q];
        xp2[2 * q] = pk2(v.x, v.y); xp2[2 * q + 1] = pk2(v.z, v.w);
    }
    __syncthreads();
    for (int rr = 0; rr < 16; rr++) {
        int k = rr * 8 + w;
        float wl = w1s[k * 32 + lane];
        float col = 0.f;
        for (int i = 0; i < 32; i++)
            col += __shfl_sync(0xffffffffu, wl, i) * g_mom[i * 32 + lane];
        float q2 = wl * col, ml = wl * g_mom[1024 + lane];
#pragma unroll
        for (int o = 16; o; o >>= 1) {
            q2 += __shfl_down_sync(0xffffffffu, q2, o);
            ml += __shfl_down_sync(0xffffffffu, ml, o);
        }
        if (lane == 0) {
            ml *= invN;
            float bk = b1[k], mu = ml + bk;
            float var = q2 * invN + 2.f * bk * ml + bk * bk - mu * mu;
            float a = g1[k] * rsqrtf(var + 1e-5f);
            cf[k] = a;
            cf[K1 + k] = fmaf(-mu, a, be1[k]);
        }
    }
    __syncthreads();
    for (int cc = 0; cc < 4; cc++) {
#pragma unroll 2
        for (int chp = 0; chp < 16; chp++) {
            int ch0 = cc * 32 + chp * 2;
            float an[2];
#pragma unroll
            for (int s = 0; s < 2; s++) {
                int ch = ch0 + s;
                const u64* wr = (const u64*)(w1s + ch * CIN);
                u64 a = 0ull;
#pragma unroll
                for (int q = 0; q < 16; q++) fma2(a, xp2[q], wr[q]);
                float2 f = upk2(a);
                float h = f.x + f.y + cf[2 * K1 + ch];
                an[s] = fmaxf(fmaf(cf[ch], h, cf[K1 + ch]), 0.f);
            }
            __nv_bfloat162 h2 = __floats2bfloat162_rn(an[0], an[1]);
            float r0 = an[0] - __low2float(h2);
            float r1 = an[1] - __high2float(h2);
            __nv_bfloat162 l2 = __floats2bfloat162_rn(r0, r1);
            uint32_t hu, lu; memcpy(&hu, &h2, 4); memcpy(&lu, &l2, 4);
            sh_hi[tid * 17 + chp] = hu;
            sh_lo[tid * 17 + chp] = lu;
        }
        __syncthreads();
        for (int i = tid; i < 1024; i += 256) {
            int pp = i >> 2, q4 = i & 3;
            uint4 vh, vl;
            vh.x = sh_hi[pp * 17 + q4 * 4];     vh.y = sh_hi[pp * 17 + q4 * 4 + 1];
            vh.z = sh_hi[pp * 17 + q4 * 4 + 2]; vh.w = sh_hi[pp * 17 + q4 * 4 + 3];
            vl.x = sh_lo[pp * 17 + q4 * 4];     vl.y = sh_lo[pp * 17 + q4 * 4 + 1];
            vl.z = sh_lo[pp * 17 + q4 * 4 + 2]; vl.w = sh_lo[pp * 17 + q4 * 4 + 3];
            g_Ah4[(p0 + pp) * 16 + cc * 4 + q4] = vh;
            g_Al4[(p0 + pp) * 16 + cc * 4 + q4] = vl;
        }
        __syncthreads();
    }
}

// GEMM2: m64 tile, A resident, B 3-stage ring, 1 barrier/step; 2 blocks/SM.
// smem: A 40960, B 3x20480=61440, STG 16x128 fp32=8192, bias 2048. total 112640.
#define SM_A   0
#define SM_B   40960
#define SM_STG 102400
#define SM_BS  110592
#define SM_TOTAL 112640

__global__ __launch_bounds__(256, 2) void k_gemm2_mma(const float* __restrict__ b2, int N) {
    extern __shared__ char smem[];
    uint32_t sb = smem_u32(smem);
    int tid = threadIdx.x, lane = tid & 31, wid = tid >> 5;
    int wm = wid >> 2, wn = wid & 3;
    size_t p0 = (size_t)blockIdx.x * 64;
    float* bs = (float*)(smem + SM_BS);
    bs[tid] = b2[tid]; bs[256 + tid] = b2[256 + tid];

    for (int e = tid; e < 2048; e += 256) {
        int ck = e >> 9, hl = (e >> 8) & 1, r = (e >> 2) & 63, c2 = e & 3;
        uint32_t dst = sb + (uint32_t)(ck * 10240 + hl * 5120 + r * 80 + c2 * 16);
        const char* base = hl ? (const char*)g_Al4 : (const char*)g_Ah4;
        cpasync16(dst, base + (p0 + r) * 256 + ck * 64 + c2 * 16);
    }
    CP_COMMIT();
    auto copyB = [&](int step) {
        int nb = step >> 2, ck = step & 3, buf = step % 3;
        for (int e = tid; e < 1024; e += 256) {
            int hl = e >> 9, r = (e >> 2) & 127, c2 = e & 3;
            uint32_t dst = sb + SM_B + (uint32_t)(buf * 20480 + hl * 10240 + r * 80 + c2 * 16);
            const char* base = hl ? (const char*)g_Bl4 : (const char*)g_Bh4;
            cpasync16(dst, base + (size_t)(nb * 128 + r) * 256 + ck * 64 + c2 * 16);
        }
        CP_COMMIT();
    };
    copyB(0); copyB(1);

    uint32_t laneOff = (uint32_t)((lane & 15) * 80 + (lane >> 4) * 16);
    float* stgf = (float*)(smem + SM_STG);
    int t4 = lane >> 2, t2 = 2 * (lane & 3);
    int col = tid & 127, half = tid >> 7;

    for (int nb = 0; nb < 4; nb++) {
        float acc[2][4][4];
#pragma unroll
        for (int mi = 0; mi < 2; mi++)
#pragma unroll
            for (int c = 0; c < 4; c++)
#pragma unroll
                for (int j = 0; j < 4; j++) acc[mi][c][j] = 0.f;
        for (int ck = 0; ck < 4; ck++) {
            int step = nb * 4 + ck;
            if (step < 15) asm volatile("cp.async.wait_group 1;" ::: "memory");
            else           asm volatile("cp.async.wait_group 0;" ::: "memory");
            __syncthreads();
            if (step + 2 <= 15) copyB(step + 2);
            uint32_t aB = sb + (uint32_t)(ck * 10240) + (uint32_t)(wm * 32 * 80) + laneOff;
            uint32_t bB = sb + SM_B + (uint32_t)((step % 3) * 20480) + (uint32_t)(wn * 32 * 80) + laneOff;
#pragma unroll
            for (int ksl = 0; ksl < 2; ksl++) {
                uint32_t ah[2][4], al[2][4], bh[2][4], bl[2][4];
#pragma unroll
                for (int mi = 0; mi < 2; mi++) {
                    ldm4(ah[mi], aB + mi * 1280 + ksl * 32);
                    ldm4(al[mi], aB + 5120 + mi * 1280 + ksl * 32);
                }
#pragma unroll
                for (int nj = 0; nj < 2; nj++) {
                    ldm4(bh[nj], bB + nj * 1280 + ksl * 32);
                    ldm4(bl[nj], bB + 10240 + nj * 1280 + ksl * 32);
                }
                // 3 sweeps: dep distance 8 issues per acc
#pragma unroll
                for (int mi = 0; mi < 2; mi++)
#pragma unroll
                    for (int nj = 0; nj < 2; nj++)
#pragma unroll
                        for (int s = 0; s < 2; s++)
                            mma16816(acc[mi][nj * 2 + s], ah[mi], bh[nj][s], bh[nj][s + 2]);
#pragma unroll
                for (int mi = 0; mi < 2; mi++)
#pragma unroll
                    for (int nj = 0; nj < 2; nj++)
#pragma unroll
                        for (int s = 0; s < 2; s++)
                            mma16816(acc[mi][nj * 2 + s], ah[mi], bl[nj][s], bl[nj][s + 2]);
#pragma unroll
                for (int mi = 0; mi < 2; mi++)
#pragma unroll
                    for (int nj = 0; nj < 2; nj++)
#pragma unroll
                        for (int s = 0; s < 2; s++)
                            mma16816(acc[mi][nj * 2 + s], al[mi], bh[nj][s], bh[nj][s + 2]);
            }
        }
        // epilogue: 4 passes of 16 rows through 8KB stage, fused BN2 stats
        int n0 = nb * 128;
        float sst = 0.f, qst = 0.f;
        float bias = bs[n0 + col];
#pragma unroll
        for (int pass = 0; pass < 4; pass++) {
            __syncthreads();
            if (wm == (pass >> 1)) {
                int mi = pass & 1;
#pragma unroll
                for (int c = 0; c < 4; c++) {
                    int nn = wn * 32 + c * 8 + t2;
                    float* d = acc[mi][c];
                    *(float2*)&stgf[t4 * 128 + (nn ^ ((t4 & 7) << 2))] = make_float2(d[0], d[1]);
                    int m2 = t4 + 8;
                    *(float2*)&stgf[m2 * 128 + (nn ^ ((m2 & 7) << 2))] = make_float2(d[2], d[3]);
                }
            }
            __syncthreads();
#pragma unroll
            for (int it = 0; it < 2; it++) {
                int task = tid + it * 256;
                int rr = task >> 5, c4 = (task & 31) * 4;
                float4 v = *(const float4*)&stgf[rr * 128 + (c4 ^ ((rr & 7) << 2))];
                float4 bb = *(const float4*)&bs[n0 + c4];
                v.x += bb.x; v.y += bb.y; v.z += bb.z; v.w += bb.w;
                *(float4*)&g_att[(p0 + pass * 16 + rr) * K2 + n0 + c4] = v;
            }
#pragma unroll
            for (int r = half * 8; r < half * 8 + 8; r++) {
                float v = stgf[r * 128 + (col ^ ((r & 7) << 2))] + bias;
                sst += v; qst += v * v;
            }
        }
        __syncthreads();
        atomicAdd(&g_s2[n0 + col], sst);
        atomicAdd(&g_s2[K2 + n0 + col], qst);
    }
}

__global__ void k_fin2(const float* __restrict__ g2, const float* __restrict__ be2, float invN) {
    int k = threadIdx.x;
    float mu = g_s2[k] * invN;
    float var = g_s2[K2 + k] * invN - mu * mu;
    float a = g2[k] * rsqrtf(var + 1e-5f);
    g_bn2[k] = a;
    g_bn2[K2 + k] = fmaf(-mu, a, be2[k]);
}

// pool via HMMA, cp.async-staged att chunks (64 points)
#define PRAW 0
#define PIMG 65536
#define PIMX 100352
#define PBN  110592
#define PSM_TOTAL 111616

__global__ __launch_bounds__(256, 2) void k_pool_mma(const float* __restrict__ x,
                                                     float* __restrict__ gp_out, int L) {
    extern __shared__ char smem[];
    uint32_t sb = smem_u32(smem);
    int tid = threadIdx.x, lane = tid & 31, wid = tid >> 5;
    int wm = wid >> 1, wn = wid & 1;
    int b = blockIdx.x, kg = blockIdx.y, z = blockIdx.z;
    int k0 = kg * 128;
    int lsl = L >> 4;
    size_t pbase = (size_t)b * L + (size_t)z * lsl;
    float* a2s = (float*)(smem + PBN);
    float* c2s = a2s + 128;
    if (tid < 128) { a2s[tid] = g_bn2[k0 + tid]; c2s[tid] = g_bn2[K2 + k0 + tid]; }

    int kq = tid & 31;
    float gpl[4] = {0.f, 0.f, 0.f, 0.f};
    float acc[2][2][4];
#pragma unroll
    for (int mi = 0; mi < 2; mi++)
#pragma unroll
        for (int nj = 0; nj < 2; nj++)
#pragma unroll
            for (int j = 0; j < 4; j++) acc[mi][nj][j] = 0.f;

    int trow = (lane & 7) + ((lane >> 4) << 3);
    int tcol = (lane >> 3) & 1;
    int nchunks = lsl >> 6;

    auto loadraw = [&](int ch, int buf) {
        size_t row0 = pbase + (size_t)ch * 64;
        for (int e = tid; e < 2048; e += 256) {
            int p = e >> 5, c16 = e & 31;
            cpasync16(sb + PRAW + (uint32_t)(buf * 32768 + p * 512 + c16 * 16),
                      (const char*)&g_att[(row0 + p) * K2 + k0] + c16 * 16);
        }
        CP_COMMIT();
    };
    loadraw(0, 0);

    for (int ch = 0; ch < nchunks; ch++) {
        int buf = ch & 1;
        asm volatile("cp.async.wait_group 0;" ::: "memory");
        __syncthreads();
        if (ch + 1 < nchunks) loadraw(ch + 1, buf ^ 1);
        const float* raw = (const float*)(smem + PRAW + buf * 32768);
        for (int i = tid; i < 2048; i += 256) {
            int p = i >> 5;
            float4 v = *(const float4*)(raw + p * 128 + kq * 4);
            float f0 = fmaxf(fmaf(a2s[kq * 4],     v.x, c2s[kq * 4]),     0.f);
            float f1 = fmaxf(fmaf(a2s[kq * 4 + 1], v.y, c2s[kq * 4 + 1]), 0.f);
            float f2 = fmaxf(fmaf(a2s[kq * 4 + 2], v.z, c2s[kq * 4 + 2]), 0.f);
            float f3 = fmaxf(fmaf(a2s[kq * 4 + 3], v.w, c2s[kq * 4 + 3]), 0.f);
            gpl[0] += f0; gpl[1] += f1; gpl[2] += f2; gpl[3] += f3;
            __nv_bfloat162 h01 = __floats2bfloat162_rn(f0, f1);
            __nv_bfloat162 h23 = __floats2bfloat162_rn(f2, f3);
            __nv_bfloat162 l01 = __floats2bfloat162_rn(f0 - __low2float(h01), f1 - __high2float(h01));
            __nv_bfloat162 l23 = __floats2bfloat162_rn(f2 - __low2float(h23), f3 - __high2float(h23));
            uint2 hv, lv;
            memcpy(&hv.x, &h01, 4); memcpy(&hv.y, &h23, 4);
            memcpy(&lv.x, &l01, 4); memcpy(&lv.y, &l23, 4);
            *(uint2*)(smem + PIMG + p * 272 + kq * 8) = hv;
            *(uint2*)(smem + PIMG + 17408 + p * 272 + kq * 8) = lv;
        }
        for (int i = tid; i < 512; i += 256) {
            int p = i >> 3, cq = i & 7;
            float4 v = *(const float4*)&x[(pbase + (size_t)ch * 64 + p) * CIN + cq * 4];
            __nv_bfloat162 h01 = __floats2bfloat162_rn(v.x, v.y);
            __nv_bfloat162 h23 = __floats2bfloat162_rn(v.z, v.w);
            __nv_bfloat162 l01 = __floats2bfloat162_rn(v.x - __low2float(h01), v.y - __high2float(h01));
            __nv_bfloat162 l23 = __floats2bfloat162_rn(v.z - __low2float(h23), v.w - __high2float(h23));
            uint2 hv, lv;
            memcpy(&hv.x, &h01, 4); memcpy(&hv.y, &h23, 4);
            memcpy(&lv.x, &l01, 4); memcpy(&lv.y, &l23, 4);
            *(uint2*)(smem + PIMX + p * 80 + cq * 8) = hv;
            *(uint2*)(smem + PIMX + 5120 + p * 80 + cq * 8) = lv;
        }
        __syncthreads();
#pragma unroll
        for (int ps = 0; ps < 4; ps++) {
            uint32_t arow = sb + PIMG + (uint32_t)((ps * 16 + trow) * 272 + tcol * 16);
            uint32_t xrow = sb + PIMX + (uint32_t)((ps * 16 + trow) * 80 + wn * 32 + tcol * 16);
            uint32_t ah[2][4], al[2][4];
#pragma unroll
            for (int mi = 0; mi < 2; mi++) {
                uint32_t kb = (uint32_t)((wm * 32 + mi * 16) * 2);
                ldm4t(ah[mi], arow + kb);
                ldm4t(al[mi], arow + 17408 + kb);
            }
            uint32_t xh[4], xl[4];
            ldm4t(xh, xrow);
            ldm4t(xl, xrow + 5120);
#pragma unroll
            for (int mi = 0; mi < 2; mi++)
#pragma unroll
                for (int nj = 0; nj < 2; nj++) {
                    float* d = acc[mi][nj];
                    mma16816(d, ah[mi], xh[nj], xh[nj + 2]);
                    mma16816(d, ah[mi], xl[nj], xl[nj + 2]);
                    mma16816(d, al[mi], xh[nj], xh[nj + 2]);
                }
        }
    }
    int g = lane >> 2, t2 = 2 * (lane & 3);
#pragma unroll
    for (int mi = 0; mi < 2; mi++) {
        int kch = k0 + wm * 32 + mi * 16 + g;
#pragma unroll
        for (int nj = 0; nj < 2; nj++) {
            int c = wn * 16 + nj * 8 + t2;
            float* d = acc[mi][nj];
            atomicAdd(&g_pooled[((size_t)b * K2 + kch) * CIN + c], d[0]);
            atomicAdd(&g_pooled[((size_t)b * K2 + kch) * CIN + c + 1], d[1]);
            atomicAdd(&g_pooled[((size_t)b * K2 + kch + 8) * CIN + c], d[2]);
            atomicAdd(&g_pooled[((size_t)b * K2 + kch + 8) * CIN + c + 1], d[3]);
        }
    }
#pragma unroll
    for (int j = 0; j < 4; j++)
        atomicAdd(&gp_out[b * K2 + k0 + kq * 4 + j], gpl[j]);
}

__global__ __launch_bounds__(256) void k_fc(const float* __restrict__ wf,
                                            const float* __restrict__ bf,
                                            int B, float invL) {
    int j = blockIdx.x, tid = threadIdx.x;
    const float* wrow = wf + (size_t)j * (K2 * CIN);
    float acc[MAXB];
#pragma unroll
    for (int b = 0; b < MAXB; b++) acc[b] = 0.f;
    for (int i = tid; i < K2 * CIN; i += 256) {
        float w = wrow[i];
#pragma unroll
        for (int b = 0; b < MAXB; b++)
            if (b < B) acc[b] += w * g_pooled[(size_t)b * (K2 * CIN) + i];
    }
    __shared__ float red[8][MAXB];
    int lane = tid & 31, w = tid >> 5;
#pragma unroll
    for (int b = 0; b < MAXB; b++) {
        float v = acc[b];
#pragma unroll
        for (int o = 16; o; o >>= 1) v += __shfl_down_sync(0xffffffffu, v, o);
        if (lane == 0) red[w][b] = v;
    }
    __syncthreads();
    if (tid < B) {
        float ssum = 0.f;
        for (int i = 0; i < 8; i++) ssum += red[i][tid];
        g_resraw[tid * FCD + j] = fmaf(ssum, invL, bf[j]);
    }
}

__global__ void k_final(float* __restrict__ outp, const float* __restrict__ gf,
                        const float* __restrict__ bef, int B, int L) {
    int j = threadIdx.x;
    __shared__ float rows[MAXB];
    if (j < B) rows[j] = 0.f;
    __syncthreads();
    float v[MAXB];
    float s = 0.f, q = 0.f;
    for (int b = 0; b < B; b++) {
        v[b] = g_resraw[b * FCD + j];
        s += v[b]; q += v[b] * v[b];
    }
    float invB = 1.f / (float)B;
    float mu = s * invB;
    float var = q * invB - mu * mu;
    float a = gf[j] * rsqrtf(var + 1e-5f);
    float c = fmaf(-mu, a, bef[j]);
    for (int b = 0; b < B; b++) {
        v[b] = fmaf(a, v[b], c);
        atomicAdd(&rows[b], v[b] * v[b]);
    }
    __syncthreads();
    for (int b = 0; b < B; b++)
        outp[b * FCD + j] = v[b] / fmaxf(sqrtf(rows[b]), 1e-12f);
    if (j < B) outp[B * FCD + B * K2 + j] = (float)L;
}

extern "C" void kernel_launch(void* const* d_in, const int* in_sizes, int n_in,
                              void* d_out, int out_size) {
    const float* x   = (const float*)d_in[0];
    const float* w1  = (const float*)d_in[1];
    const float* b1  = (const float*)d_in[2];
    const float* g1  = (const float*)d_in[3];
    const float* be1 = (const float*)d_in[4];
    const float* w2  = (const float*)d_in[5];
    const float* b2  = (const float*)d_in[6];
    const float* g2  = (const float*)d_in[7];
    const float* be2 = (const float*)d_in[8];
    const float* wf  = (const float*)d_in[9];
    const float* bf  = (const float*)d_in[10];
    const float* gf  = (const float*)d_in[11];
    const float* bef = (const float*)d_in[12];
    float* outp = (float*)d_out;

    int N = in_sizes[0] / CIN;
    int B = out_size / (FCD + K2 + 1);
    int L = N / B;
    float invN = 1.f / (float)N;
    float invL = 1.f / (float)L;

    cudaFuncSetAttribute(k_gemm2_mma, cudaFuncAttributeMaxDynamicSharedMemorySize, SM_TOTAL);
    cudaFuncSetAttribute(k_pool_mma, cudaFuncAttributeMaxDynamicSharedMemorySize, PSM_TOTAL);

    k_zero<<<(B * K2 * CIN + 255) / 256, 256>>>(outp, B, w2);
    k_moments<<<N / 8192, 256>>>(x, N);
    k_gemm1f<<<N / 256, 256>>>(x, w1, b1, g1, be1, invN, N);
    k_gemm2_mma<<<N / 64, 256, SM_TOTAL>>>(b2, N);
    k_fin2<<<1, K2>>>(g2, be2, invN);
    k_pool_mma<<<dim3(B, K2 / 128, 16), 256, PSM_TOTAL>>>(x, outp + B * FCD, L);
    k_fc<<<FCD, 256>>>(wf, bf, B, invL);
    k_final<<<1, FCD>>>(outp, gf, bef, B, L);
}

// round 16
// speedup vs baseline: 1.4844x; 1.4844x over previous
#include <cuda_runtime.h>
#include <cuda_bf16.h>
#include <cstdint>
#include <cstddef>
#include <cstring>

#define CIN 32
#define K1  128
#define K2  512
#define FCD 256
#define MAXN 524288
#define MAXB 16

typedef unsigned long long u64;

__device__ float g_att[(size_t)MAXN * K2];
__device__ uint4 g_Ah4[(size_t)MAXN * 16];   // bf16 hi, row-major [p][128]
__device__ uint4 g_Al4[(size_t)MAXN * 16];   // bf16 lo
__device__ uint4 g_Bh4[K2 * 16];             // w2 hi, [n][128]
__device__ uint4 g_Bl4[K2 * 16];
__device__ float g_mom[1088];                // Sxx[32*32] + sums[32]
__device__ float g_s2[2 * K2];
__device__ float g_pooled[MAXB * K2 * CIN];
__device__ float g_resraw[MAXB * FCD];

__device__ __forceinline__ u64 pk2(float lo, float hi) {
    u64 r; asm("mov.b64 %0, {%1, %2};" : "=l"(r) : "f"(lo), "f"(hi)); return r;
}
__device__ __forceinline__ void fma2(u64 &d, u64 a, u64 b) {
    asm("fma.rn.f32x2 %0, %1, %2, %0;" : "+l"(d) : "l"(a), "l"(b));
}
__device__ __forceinline__ float2 upk2(u64 v) {
    float lo, hi; asm("mov.b64 {%0, %1}, %2;" : "=f"(lo), "=f"(hi) : "l"(v));
    return make_float2(lo, hi);
}
__device__ __forceinline__ uint32_t smem_u32(const void* p) {
    uint32_t a;
    asm("{ .reg .u64 t; cvta.to.shared.u64 t, %1; cvt.u32.u64 %0, t; }" : "=r"(a) : "l"(p));
    return a;
}
__device__ __forceinline__ void cpasync16(uint32_t dst, const void* src) {
    asm volatile("cp.async.cg.shared.global [%0], [%1], 16;" :: "r"(dst), "l"(src));
}
#define CP_COMMIT() asm volatile("cp.async.commit_group;" ::: "memory")

__device__ __forceinline__ void ldm4(uint32_t* r, uint32_t a) {
    asm volatile("ldmatrix.sync.aligned.m8n8.x4.shared.b16 {%0,%1,%2,%3}, [%4];"
        : "=r"(r[0]), "=r"(r[1]), "=r"(r[2]), "=r"(r[3]) : "r"(a));
}
__device__ __forceinline__ void ldm4t(uint32_t* r, uint32_t a) {
    asm volatile("ldmatrix.sync.aligned.m8n8.x4.trans.shared.b16 {%0,%1,%2,%3}, [%4];"
        : "=r"(r[0]), "=r"(r[1]), "=r"(r[2]), "=r"(r[3]) : "r"(a));
}
__device__ __forceinline__ void mma16816(float* d, const uint32_t* a, uint32_t b0, uint32_t b1) {
    asm volatile("mma.sync.aligned.m16n8k16.row.col.f32.bf16.bf16.f32 "
        "{%0,%1,%2,%3}, {%4,%5,%6,%7}, {%8,%9}, {%0,%1,%2,%3};"
        : "+f"(d[0]), "+f"(d[1]), "+f"(d[2]), "+f"(d[3])
        : "r"(a[0]), "r"(a[1]), "r"(a[2]), "r"(a[3]), "r"(b0), "r"(b1));
}

__device__ __forceinline__ void split8(const float* v, uint32_t* hw, uint32_t* lw) {
#pragma unroll
    for (int j = 0; j < 4; j++) {
        float f0 = v[2 * j], f1 = v[2 * j + 1];
        __nv_bfloat162 h2 = __floats2bfloat162_rn(f0, f1);
        float r0 = f0 - __low2float(h2);
        float r1 = f1 - __high2float(h2);
        __nv_bfloat162 l2 = __floats2bfloat162_rn(r0, r1);
        memcpy(&hw[j], &h2, 4); memcpy(&lw[j], &l2, 4);
    }
}

// zero + w2 split prep
__global__ void k_zero(float* outp, int B, const float* __restrict__ w2) {
    int i = blockIdx.x * blockDim.x + threadIdx.x;
    if (i < B * K2 * CIN) g_pooled[i] = 0.f;
    if (i < 1088) g_mom[i] = 0.f;
    if (i < 2 * K2) g_s2[i] = 0.f;
    if (i < B * K2) outp[B * FCD + i] = 0.f;
    if (i < K2 * 16) {
        int n = i >> 4, q = i & 15;
        float v[8];
        *(float4*)v       = *(const float4*)(w2 + (size_t)n * 128 + q * 8);
        *(float4*)(v + 4) = *(const float4*)(w2 + (size_t)n * 128 + q * 8 + 4);
        uint32_t hw[4], lw[4];
        split8(v, hw, lw);
        g_Bh4[n * 16 + q] = make_uint4(hw[0], hw[1], hw[2], hw[3]);
        g_Bl4[n * 16 + q] = make_uint4(lw[0], lw[1], lw[2], lw[3]);
    }
}

// x moments
__global__ __launch_bounds__(256) void k_moments(const float* __restrict__ x, int N) {
    __shared__ float xs[128 * 34];
    int tid = threadIdx.x, tt = tid & 31, rep = tid >> 5;
    int i0 = (tt >> 2) * 4, j0 = (tt & 3) * 8;
    int npb = N / gridDim.x;
    size_t base = (size_t)blockIdx.x * npb;
    u64 acc[4][4];
#pragma unroll
    for (int a = 0; a < 4; a++)
#pragma unroll
        for (int q = 0; q < 4; q++) acc[a][q] = 0ull;
    float ssum[4] = {0.f, 0.f, 0.f, 0.f};
    for (int t = 0; t < npb / 128; t++) {
        __syncthreads();
        for (int i = tid; i < 1024; i += 256) {
            int p = i >> 3, q = i & 7;
            float4 v = *(const float4*)&x[(base + t * 128 + p) * CIN + q * 4];
            *(float2*)&xs[p * 34 + q * 4]     = make_float2(v.x, v.y);
            *(float2*)&xs[p * 34 + q * 4 + 2] = make_float2(v.z, v.w);
        }
        __syncthreads();
        for (int pp = 0; pp < 16; pp++) {
            const float* xr = &xs[(rep * 16 + pp) * 34];
            float xi[4]; u64 xj[4];
#pragma unroll
            for (int a = 0; a < 4; a++) xi[a] = xr[i0 + a];
#pragma unroll
            for (int q = 0; q < 4; q++) xj[q] = *(const u64*)&xr[j0 + 2 * q];
#pragma unroll
            for (int a = 0; a < 4; a++) {
                u64 ap = pk2(xi[a], xi[a]);
#pragma unroll
                for (int q = 0; q < 4; q++) fma2(acc[a][q], ap, xj[q]);
            }
            if ((tt & 3) == 0)
#pragma unroll
                for (int a = 0; a < 4; a++) ssum[a] += xi[a];
        }
    }
#pragma unroll
    for (int a = 0; a < 4; a++)
#pragma unroll
        for (int q = 0; q < 4; q++) {
            float2 f = upk2(acc[a][q]);
            atomicAdd(&g_mom[(i0 + a) * 32 + j0 + 2 * q], f.x);
            atomicAdd(&g_mom[(i0 + a) * 32 + j0 + 2 * q + 1], f.y);
        }
    if ((tt & 3) == 0)
#pragma unroll
        for (int a = 0; a < 4; a++) atomicAdd(&g_mom[1024 + i0 + a], ssum[a]);
}

// fused GEMM1 + analytic BN1 + relu + bf16 hi/lo split -> A images
__global__ __launch_bounds__(256) void k_gemm1f(const float* __restrict__ x,
                                                const float* __restrict__ w1,
                                                const float* __restrict__ b1,
                                                const float* __restrict__ g1,
                                                const float* __restrict__ be1,
                                                float invN, int N) {
    __shared__ __align__(16) float w1s[K1 * CIN];
    __shared__ float cf[3 * K1];
    __shared__ uint32_t sh_hi[256 * 17];
    __shared__ uint32_t sh_lo[256 * 17];
    int tid = threadIdx.x, lane = tid & 31, w = tid >> 5;
    for (int i = tid; i < K1 * CIN; i += 256) w1s[i] = w1[i];
    if (tid < K1) cf[2 * K1 + tid] = b1[tid];
    size_t p0 = (size_t)blockIdx.x * 256;
    u64 xp2[16];
    const float4* xp = (const float4*)(x + (p0 + tid) * CIN);
#pragma unroll
    for (int q = 0; q < 8; q++) {
        float4 v = xp[q];
        xp2[2 * q] = pk2(v.x, v.y); xp2[2 * q + 1] = pk2(v.z, v.w);
    }
    __syncthreads();
    for (int rr = 0; rr < 16; rr++) {
        int k = rr * 8 + w;
        float wl = w1s[k * 32 + lane];
        float col = 0.f;
        for (int i = 0; i < 32; i++)
            col += __shfl_sync(0xffffffffu, wl, i) * g_mom[i * 32 + lane];
        float q2 = wl * col, ml = wl * g_mom[1024 + lane];
#pragma unroll
        for (int o = 16; o; o >>= 1) {
            q2 += __shfl_down_sync(0xffffffffu, q2, o);
            ml += __shfl_down_sync(0xffffffffu, ml, o);
        }
        if (lane == 0) {
            ml *= invN;
            float bk = b1[k], mu = ml + bk;
            float var = q2 * invN + 2.f * bk * ml + bk * bk - mu * mu;
            float a = g1[k] * rsqrtf(var + 1e-5f);
            cf[k] = a;
            cf[K1 + k] = fmaf(-mu, a, be1[k]);
        }
    }
    __syncthreads();
    for (int cc = 0; cc < 4; cc++) {
#pragma unroll 2
        for (int chp = 0; chp < 16; chp++) {
            int ch0 = cc * 32 + chp * 2;
            float an[2];
#pragma unroll
            for (int s = 0; s < 2; s++) {
                int ch = ch0 + s;
                const u64* wr = (const u64*)(w1s + ch * CIN);
                u64 a = 0ull;
#pragma unroll
                for (int q = 0; q < 16; q++) fma2(a, xp2[q], wr[q]);
                float2 f = upk2(a);
                float h = f.x + f.y + cf[2 * K1 + ch];
                an[s] = fmaxf(fmaf(cf[ch], h, cf[K1 + ch]), 0.f);
            }
            __nv_bfloat162 h2 = __floats2bfloat162_rn(an[0], an[1]);
            float r0 = an[0] - __low2float(h2);
            float r1 = an[1] - __high2float(h2);
            __nv_bfloat162 l2 = __floats2bfloat162_rn(r0, r1);
            uint32_t hu, lu; memcpy(&hu, &h2, 4); memcpy(&lu, &l2, 4);
            sh_hi[tid * 17 + chp] = hu;
            sh_lo[tid * 17 + chp] = lu;
        }
        __syncthreads();
        for (int i = tid; i < 1024; i += 256) {
            int pp = i >> 2, q4 = i & 3;
            uint4 vh, vl;
            vh.x = sh_hi[pp * 17 + q4 * 4];     vh.y = sh_hi[pp * 17 + q4 * 4 + 1];
            vh.z = sh_hi[pp * 17 + q4 * 4 + 2]; vh.w = sh_hi[pp * 17 + q4 * 4 + 3];
            vl.x = sh_lo[pp * 17 + q4 * 4];     vl.y = sh_lo[pp * 17 + q4 * 4 + 1];
            vl.z = sh_lo[pp * 17 + q4 * 4 + 2]; vl.w = sh_lo[pp * 17 + q4 * 4 + 3];
            g_Ah4[(p0 + pp) * 16 + cc * 4 + q4] = vh;
            g_Al4[(p0 + pp) * 16 + cc * 4 + q4] = vl;
        }
        __syncthreads();
    }
}

// GEMM2: m64 tile, A resident, B streamed; 2 blocks/SM. (R14-proven version)
#define SM_A   0
#define SM_B   40960
#define SM_STG 81920
#define SM_BS  98304
#define SM_TOTAL 100352

__global__ __launch_bounds__(256, 2) void k_gemm2_mma(const float* __restrict__ b2, int N) {
    extern __shared__ char smem[];
    uint32_t sb = smem_u32(smem);
    int tid = threadIdx.x, lane = tid & 31, wid = tid >> 5;
    int wm = wid >> 2, wn = wid & 3;
    size_t p0 = (size_t)blockIdx.x * 64;
    float* bs = (float*)(smem + SM_BS);
    bs[tid] = b2[tid]; bs[256 + tid] = b2[256 + tid];

    for (int e = tid; e < 2048; e += 256) {
        int ck = e >> 9, hl = (e >> 8) & 1, r = (e >> 2) & 63, c2 = e & 3;
        uint32_t dst = sb + (uint32_t)(ck * 10240 + hl * 5120 + r * 80 + c2 * 16);
        const char* base = hl ? (const char*)g_Al4 : (const char*)g_Ah4;
        cpasync16(dst, base + (p0 + r) * 256 + ck * 64 + c2 * 16);
    }
    CP_COMMIT();
    auto copyB = [&](int step, int buf) {
        int nb = step >> 2, ck = step & 3;
        for (int e = tid; e < 1024; e += 256) {
            int hl = e >> 9, r = (e >> 2) & 127, c2 = e & 3;
            uint32_t dst = sb + SM_B + (uint32_t)(buf * 20480 + hl * 10240 + r * 80 + c2 * 16);
            const char* base = hl ? (const char*)g_Bl4 : (const char*)g_Bh4;
            cpasync16(dst, base + (size_t)(nb * 128 + r) * 256 + ck * 64 + c2 * 16);
        }
        CP_COMMIT();
    };
    copyB(0, 0); copyB(1, 1);

    uint32_t laneOff = (uint32_t)((lane & 15) * 80 + (lane >> 4) * 16);
    float* stgf = (float*)(smem + SM_STG);
    int t4 = lane >> 2, t2 = 2 * (lane & 3);
    int col = tid & 127, half = tid >> 7;

    for (int nb = 0; nb < 4; nb++) {
        float acc[2][4][4];
#pragma unroll
        for (int mi = 0; mi < 2; mi++)
#pragma unroll
            for (int c = 0; c < 4; c++)
#pragma unroll
                for (int j = 0; j < 4; j++) acc[mi][c][j] = 0.f;
        for (int ck = 0; ck < 4; ck++) {
            int step = nb * 4 + ck;
            if (step < 15) asm volatile("cp.async.wait_group 1;" ::: "memory");
            else           asm volatile("cp.async.wait_group 0;" ::: "memory");
            __syncthreads();
            uint32_t aB = sb + (uint32_t)(ck * 10240) + (uint32_t)(wm * 32 * 80) + laneOff;
            uint32_t bB = sb + SM_B + (uint32_t)((step & 1) * 20480) + (uint32_t)(wn * 32 * 80) + laneOff;
#pragma unroll
            for (int ksl = 0; ksl < 2; ksl++) {
                uint32_t ah[2][4], al[2][4];
#pragma unroll
                for (int mi = 0; mi < 2; mi++) {
                    ldm4(ah[mi], aB + mi * 1280 + ksl * 32);
                    ldm4(al[mi], aB + 5120 + mi * 1280 + ksl * 32);
                }
#pragma unroll
                for (int nj = 0; nj < 2; nj++) {
                    uint32_t bh[4], bl[4];
                    ldm4(bh, bB + nj * 1280 + ksl * 32);
                    ldm4(bl, bB + 10240 + nj * 1280 + ksl * 32);
#pragma unroll
                    for (int mi = 0; mi < 2; mi++)
#pragma unroll
                        for (int s = 0; s < 2; s++) {
                            float* d = acc[mi][nj * 2 + s];
                            mma16816(d, ah[mi], bh[s], bh[s + 2]);
                            mma16816(d, ah[mi], bl[s], bl[s + 2]);
                            mma16816(d, al[mi], bh[s], bh[s + 2]);
                        }
                }
            }
            __syncthreads();
            if (step + 2 <= 15) copyB(step + 2, step & 1);
        }
        int n0 = nb * 128;
        float sst = 0.f, qst = 0.f;
        float bias = bs[n0 + col];
#pragma unroll
        for (int pass = 0; pass < 2; pass++) {
            if (wm == pass) {
#pragma unroll
                for (int mi = 0; mi < 2; mi++) {
                    int mB = mi * 16 + t4;
#pragma unroll
                    for (int c = 0; c < 4; c++) {
                        int nn = wn * 32 + c * 8 + t2;
                        float* d = acc[mi][c];
                        *(float2*)&stgf[mB * 128 + (nn ^ ((mB & 7) << 2))] = make_float2(d[0], d[1]);
                        int m2 = mB + 8;
                        *(float2*)&stgf[m2 * 128 + (nn ^ ((m2 & 7) << 2))] = make_float2(d[2], d[3]);
                    }
                }
            }
            __syncthreads();
#pragma unroll
            for (int it = 0; it < 4; it++) {
                int task = tid + it * 256;
                int rr = task >> 5, c4 = (task & 31) * 4;
                float4 v = *(const float4*)&stgf[rr * 128 + (c4 ^ ((rr & 7) << 2))];
                float4 bb = *(const float4*)&bs[n0 + c4];
                v.x += bb.x; v.y += bb.y; v.z += bb.z; v.w += bb.w;
                *(float4*)&g_att[(p0 + pass * 32 + rr) * K2 + n0 + c4] = v;
            }
#pragma unroll 4
            for (int r = half * 16; r < half * 16 + 16; r++) {
                float v = stgf[r * 128 + (col ^ ((r & 7) << 2))] + bias;
                sst += v; qst += v * v;
            }
            __syncthreads();
        }
        atomicAdd(&g_s2[n0 + col], sst);
        atomicAdd(&g_s2[K2 + n0 + col], qst);
    }
}

// pool via HMMA, cp.async-staged att chunks; BN2 coefs computed inline from g_s2
#define PRAW 0
#define PIMG 65536
#define PIMX 100352
#define PBN  110592
#define PSM_TOTAL 111616

__global__ __launch_bounds__(256, 2) void k_pool_mma(const float* __restrict__ x,
                                                     float* __restrict__ gp_out,
                                                     const float* __restrict__ g2,
                                                     const float* __restrict__ be2,
                                                     float invN, int L) {
    extern __shared__ char smem[];
    uint32_t sb = smem_u32(smem);
    int tid = threadIdx.x, lane = tid & 31, wid = tid >> 5;
    int wm = wid >> 1, wn = wid & 1;
    int b = blockIdx.x, kg = blockIdx.y, z = blockIdx.z;
    int k0 = kg * 128;
    int lsl = L >> 4;
    size_t pbase = (size_t)b * L + (size_t)z * lsl;
    float* a2s = (float*)(smem + PBN);
    float* c2s = a2s + 128;
    if (tid < 128) {
        int k = k0 + tid;
        float mu = g_s2[k] * invN;
        float var = g_s2[K2 + k] * invN - mu * mu;
        float a = g2[k] * rsqrtf(var + 1e-5f);
        a2s[tid] = a;
        c2s[tid] = fmaf(-mu, a, be2[k]);
    }

    int kq = tid & 31;
    float gpl[4] = {0.f, 0.f, 0.f, 0.f};
    float acc[2][2][4];
#pragma unroll
    for (int mi = 0; mi < 2; mi++)
#pragma unroll
        for (int nj = 0; nj < 2; nj++)
#pragma unroll
            for (int j = 0; j < 4; j++) acc[mi][nj][j] = 0.f;

    int trow = (lane & 7) + ((lane >> 4) << 3);
    int tcol = (lane >> 3) & 1;
    int nchunks = lsl >> 6;

    auto loadraw = [&](int ch, int buf) {
        size_t row0 = pbase + (size_t)ch * 64;
        for (int e = tid; e < 2048; e += 256) {
            int p = e >> 5, c16 = e & 31;
            cpasync16(sb + PRAW + (uint32_t)(buf * 32768 + p * 512 + c16 * 16),
                      (const char*)&g_att[(row0 + p) * K2 + k0] + c16 * 16);
        }
        CP_COMMIT();
    };
    loadraw(0, 0);

    for (int ch = 0; ch < nchunks; ch++) {
        int buf = ch & 1;
        asm volatile("cp.async.wait_group 0;" ::: "memory");
        __syncthreads();
        if (ch + 1 < nchunks) loadraw(ch + 1, buf ^ 1);
        const float* raw = (const float*)(smem + PRAW + buf * 32768);
        for (int i = tid; i < 2048; i += 256) {
            int p = i >> 5;
            float4 v = *(const float4*)(raw + p * 128 + kq * 4);
            float f0 = fmaxf(fmaf(a2s[kq * 4],     v.x, c2s[kq * 4]),     0.f);
            float f1 = fmaxf(fmaf(a2s[kq * 4 + 1], v.y, c2s[kq * 4 + 1]), 0.f);
            float f2 = fmaxf(fmaf(a2s[kq * 4 + 2], v.z, c2s[kq * 4 + 2]), 0.f);
            float f3 = fmaxf(fmaf(a2s[kq * 4 + 3], v.w, c2s[kq * 4 + 3]), 0.f);
            gpl[0] += f0; gpl[1] += f1; gpl[2] += f2; gpl[3] += f3;
            __nv_bfloat162 h01 = __floats2bfloat162_rn(f0, f1);
            __nv_bfloat162 h23 = __floats2bfloat162_rn(f2, f3);
            __nv_bfloat162 l01 = __floats2bfloat162_rn(f0 - __low2float(h01), f1 - __high2float(h01));
            __nv_bfloat162 l23 = __floats2bfloat162_rn(f2 - __low2float(h23), f3 - __high2float(h23));
            uint2 hv, lv;
            memcpy(&hv.x, &h01, 4); memcpy(&hv.y, &h23, 4);
            memcpy(&lv.x, &l01, 4); memcpy(&lv.y, &l23, 4);
            *(uint2*)(smem + PIMG + p * 272 + kq * 8) = hv;
            *(uint2*)(smem + PIMG + 17408 + p * 272 + kq * 8) = lv;
        }
        for (int i = tid; i < 512; i += 256) {
            int p = i >> 3, cq = i & 7;
            float4 v = *(const float4*)&x[(pbase + (size_t)ch * 64 + p) * CIN + cq * 4];
            __nv_bfloat162 h01 = __floats2bfloat162_rn(v.x, v.y);
            __nv_bfloat162 h23 = __floats2bfloat162_rn(v.z, v.w);
            __nv_bfloat162 l01 = __floats2bfloat162_rn(v.x - __low2float(h01), v.y - __high2float(h01));
            __nv_bfloat162 l23 = __floats2bfloat162_rn(v.z - __low2float(h23), v.w - __high2float(h23));
            uint2 hv, lv;
            memcpy(&hv.x, &h01, 4); memcpy(&hv.y, &h23, 4);
            memcpy(&lv.x, &l01, 4); memcpy(&lv.y, &l23, 4);
            *(uint2*)(smem + PIMX + p * 80 + cq * 8) = hv;
            *(uint2*)(smem + PIMX + 5120 + p * 80 + cq * 8) = lv;
        }
        __syncthreads();
#pragma unroll
        for (int ps = 0; ps < 4; ps++) {
            uint32_t arow = sb + PIMG + (uint32_t)((ps * 16 + trow) * 272 + tcol * 16);
            uint32_t xrow = sb + PIMX + (uint32_t)((ps * 16 + trow) * 80 + wn * 32 + tcol * 16);
            uint32_t ah[2][4], al[2][4];
#pragma unroll
            for (int mi = 0; mi < 2; mi++) {
                uint32_t kb = (uint32_t)((wm * 32 + mi * 16) * 2);
                ldm4t(ah[mi], arow + kb);
                ldm4t(al[mi], arow + 17408 + kb);
            }
            uint32_t xh[4], xl[4];
            ldm4t(xh, xrow);
            ldm4t(xl, xrow + 5120);
#pragma unroll
            for (int mi = 0; mi < 2; mi++)
#pragma unroll
                for (int nj = 0; nj < 2; nj++) {
                    float* d = acc[mi][nj];
                    mma16816(d, ah[mi], xh[nj], xh[nj + 2]);
                    mma16816(d, ah[mi], xl[nj], xl[nj + 2]);
                    mma16816(d, al[mi], xh[nj], xh[nj + 2]);
                }
        }
    }
    int g = lane >> 2, t2 = 2 * (lane & 3);
#pragma unroll
    for (int mi = 0; mi < 2; mi++) {
        int kch = k0 + wm * 32 + mi * 16 + g;
#pragma unroll
        for (int nj = 0; nj < 2; nj++) {
            int c = wn * 16 + nj * 8 + t2;
            float* d = acc[mi][nj];
            atomicAdd(&g_pooled[((size_t)b * K2 + kch) * CIN + c], d[0]);
            atomicAdd(&g_pooled[((size_t)b * K2 + kch) * CIN + c + 1], d[1]);
            atomicAdd(&g_pooled[((size_t)b * K2 + kch + 8) * CIN + c], d[2]);
            atomicAdd(&g_pooled[((size_t)b * K2 + kch + 8) * CIN + c + 1], d[3]);
        }
    }
#pragma unroll
    for (int j = 0; j < 4; j++)
        atomicAdd(&gp_out[b * K2 + k0 + kq * 4 + j], gpl[j]);
}

__global__ __launch_bounds__(256) void k_fc(const float* __restrict__ wf,
                                            const float* __restrict__ bf,
                                            int B, float invL) {
    int j = blockIdx.x, tid = threadIdx.x;
    const float* wrow = wf + (size_t)j * (K2 * CIN);
    float acc[MAXB];
#pragma unroll
    for (int b = 0; b < MAXB; b++) acc[b] = 0.f;
    for (int i = tid; i < K2 * CIN; i += 256) {
        float w = wrow[i];
#pragma unroll
        for (int b = 0; b < MAXB; b++)
            if (b < B) acc[b] += w * g_pooled[(size_t)b * (K2 * CIN) + i];
    }
    __shared__ float red[8][MAXB];
    int lane = tid & 31, w = tid >> 5;
#pragma unroll
    for (int b = 0; b < MAXB; b++) {
        float v = acc[b];
#pragma unroll
        for (int o = 16; o; o >>= 1) v += __shfl_down_sync(0xffffffffu, v, o);
        if (lane == 0) red[w][b] = v;
    }
    __syncthreads();
    if (tid < B) {
        float ssum = 0.f;
        for (int i = 0; i < 8; i++) ssum += red[i][tid];
        g_resraw[tid * FCD + j] = fmaf(ssum, invL, bf[j]);
    }
}

__global__ void k_final(float* __restrict__ outp, const float* __restrict__ gf,
                        const float* __restrict__ bef, int B, int L) {
    int j = threadIdx.x;
    __shared__ float rows[MAXB];
    if (j < B) rows[j] = 0.f;
    __syncthreads();
    float v[MAXB];
    float s = 0.f, q = 0.f;
    for (int b = 0; b < B; b++) {
        v[b] = g_resraw[b * FCD + j];
        s += v[b]; q += v[b] * v[b];
    }
    float invB = 1.f / (float)B;
    float mu = s * invB;
    float var = q * invB - mu * mu;
    float a = gf[j] * rsqrtf(var + 1e-5f);
    float c = fmaf(-mu, a, bef[j]);
    for (int b = 0; b < B; b++) {
        v[b] = fmaf(a, v[b], c);
        atomicAdd(&rows[b], v[b] * v[b]);
    }
    __syncthreads();
    for (int b = 0; b < B; b++)
        outp[b * FCD + j] = v[b] / fmaxf(sqrtf(rows[b]), 1e-12f);
    if (j < B) outp[B * FCD + B * K2 + j] = (float)L;
}

extern "C" void kernel_launch(void* const* d_in, const int* in_sizes, int n_in,
                              void* d_out, int out_size) {
    const float* x   = (const float*)d_in[0];
    const float* w1  = (const float*)d_in[1];
    const float* b1  = (const float*)d_in[2];
    const float* g1  = (const float*)d_in[3];
    const float* be1 = (const float*)d_in[4];
    const float* w2  = (const float*)d_in[5];
    const float* b2  = (const float*)d_in[6];
    const float* g2  = (const float*)d_in[7];
    const float* be2 = (const float*)d_in[8];
    const float* wf  = (const float*)d_in[9];
    const float* bf  = (const float*)d_in[10];
    const float* gf  = (const float*)d_in[11];
    const float* bef = (const float*)d_in[12];
    float* outp = (float*)d_out;

    int N = in_sizes[0] / CIN;
    int B = out_size / (FCD + K2 + 1);
    int L = N / B;
    float invN = 1.f / (float)N;
    float invL = 1.f / (float)L;

    cudaFuncSetAttribute(k_gemm2_mma, cudaFuncAttributeMaxDynamicSharedMemorySize, SM_TOTAL);
    cudaFuncSetAttribute(k_pool_mma, cudaFuncAttributeMaxDynamicSharedMemorySize, PSM_TOTAL);

    k_zero<<<(B * K2 * CIN + 255) / 256, 256>>>(outp, B, w2);
    k_moments<<<N / 8192, 256>>>(x, N);
    k_gemm1f<<<N / 256, 256>>>(x, w1, b1, g1, be1, invN, N);
    k_gemm2_mma<<<N / 64, 256, SM_TOTAL>>>(b2, N);
    k_pool_mma<<<dim3(B, K2 / 128, 16), 256, PSM_TOTAL>>>(x, outp + B * FCD, g2, be2, invN, L);
    k_fc<<<FCD, 256>>>(wf, bf, B, invL);
    k_final<<<1, FCD>>>(outp, gf, bef, B, L);
}

// round 17
// speedup vs baseline: 1.5357x; 1.0346x over previous
#include <cuda_runtime.h>
#include <cuda_bf16.h>
#include <cstdint>
#include <cstddef>
#include <cstring>

#define CIN 32
#define K1  128
#define K2  512
#define FCD 256
#define MAXN 524288
#define MAXB 16
#define ZSPL 64

typedef unsigned long long u64;

__device__ float g_att[(size_t)MAXN * K2];
__device__ uint4 g_Ah4[(size_t)MAXN * 16];
__device__ uint4 g_Al4[(size_t)MAXN * 16];
__device__ uint4 g_Bh4[K2 * 16];
__device__ uint4 g_Bl4[K2 * 16];
__device__ float g_mom[1088];
__device__ float g_s2[2 * K2];
__device__ float g_pooled[MAXB * K2 * CIN];
__device__ float g_resraw[MAXB * FCD];

__device__ __forceinline__ u64 pk2(float lo, float hi) {
    u64 r; asm("mov.b64 %0, {%1, %2};" : "=l"(r) : "f"(lo), "f"(hi)); return r;
}
__device__ __forceinline__ void fma2(u64 &d, u64 a, u64 b) {
    asm("fma.rn.f32x2 %0, %1, %2, %0;" : "+l"(d) : "l"(a), "l"(b));
}
__device__ __forceinline__ float2 upk2(u64 v) {
    float lo, hi; asm("mov.b64 {%0, %1}, %2;" : "=f"(lo), "=f"(hi) : "l"(v));
    return make_float2(lo, hi);
}
__device__ __forceinline__ uint32_t smem_u32(const void* p) {
    uint32_t a;
    asm("{ .reg .u64 t; cvta.to.shared.u64 t, %1; cvt.u32.u64 %0, t; }" : "=r"(a) : "l"(p));
    return a;
}
__device__ __forceinline__ void cpasync16(uint32_t dst, const void* src) {
    asm volatile("cp.async.cg.shared.global [%0], [%1], 16;" :: "r"(dst), "l"(src));
}
#define CP_COMMIT() asm volatile("cp.async.commit_group;" ::: "memory")

__device__ __forceinline__ void ldm4(uint32_t* r, uint32_t a) {
    asm volatile("ldmatrix.sync.aligned.m8n8.x4.shared.b16 {%0,%1,%2,%3}, [%4];"
        : "=r"(r[0]), "=r"(r[1]), "=r"(r[2]), "=r"(r[3]) : "r"(a));
}
__device__ __forceinline__ void ldm4t(uint32_t* r, uint32_t a) {
    asm volatile("ldmatrix.sync.aligned.m8n8.x4.trans.shared.b16 {%0,%1,%2,%3}, [%4];"
        : "=r"(r[0]), "=r"(r[1]), "=r"(r[2]), "=r"(r[3]) : "r"(a));
}
__device__ __forceinline__ void mma16816(float* d, const uint32_t* a, uint32_t b0, uint32_t b1) {
    asm volatile("mma.sync.aligned.m16n8k16.row.col.f32.bf16.bf16.f32 "
        "{%0,%1,%2,%3}, {%4,%5,%6,%7}, {%8,%9}, {%0,%1,%2,%3};"
        : "+f"(d[0]), "+f"(d[1]), "+f"(d[2]), "+f"(d[3])
        : "r"(a[0]), "r"(a[1]), "r"(a[2]), "r"(a[3]), "r"(b0), "r"(b1));
}

__device__ __forceinline__ void split8(const float* v, uint32_t* hw, uint32_t* lw) {
#pragma unroll
    for (int j = 0; j < 4; j++) {
        float f0 = v[2 * j], f1 = v[2 * j + 1];
        __nv_bfloat162 h2 = __floats2bfloat162_rn(f0, f1);
        float r0 = f0 - __low2float(h2);
        float r1 = f1 - __high2float(h2);
        __nv_bfloat162 l2 = __floats2bfloat162_rn(r0, r1);
        memcpy(&hw[j], &h2, 4); memcpy(&lw[j], &l2, 4);
    }
}

__global__ void k_zero(float* outp, int B, const float* __restrict__ w2) {
    int i = blockIdx.x * blockDim.x + threadIdx.x;
    if (i < B * K2 * CIN) g_pooled[i] = 0.f;
    if (i < 1088) g_mom[i] = 0.f;
    if (i < 2 * K2) g_s2[i] = 0.f;
    if (i < B * K2) outp[B * FCD + i] = 0.f;
    if (i < K2 * 16) {
        int n = i >> 4, q = i & 15;
        float v[8];
        *(float4*)v       = *(const float4*)(w2 + (size_t)n * 128 + q * 8);
        *(float4*)(v + 4) = *(const float4*)(w2 + (size_t)n * 128 + q * 8 + 4);
        uint32_t hw[4], lw[4];
        split8(v, hw, lw);
        g_Bh4[n * 16 + q] = make_uint4(hw[0], hw[1], hw[2], hw[3]);
        g_Bl4[n * 16 + q] = make_uint4(lw[0], lw[1], lw[2], lw[3]);
    }
}

__global__ __launch_bounds__(256) void k_moments(const float* __restrict__ x, int N) {
    __shared__ float xs[128 * 34];
    int tid = threadIdx.x, tt = tid & 31, rep = tid >> 5;
    int i0 = (tt >> 2) * 4, j0 = (tt & 3) * 8;
    int npb = N / gridDim.x;
    size_t base = (size_t)blockIdx.x * npb;
    u64 acc[4][4];
#pragma unroll
    for (int a = 0; a < 4; a++)
#pragma unroll
        for (int q = 0; q < 4; q++) acc[a][q] = 0ull;
    float ssum[4] = {0.f, 0.f, 0.f, 0.f};
    for (int t = 0; t < npb / 128; t++) {
        __syncthreads();
        for (int i = tid; i < 1024; i += 256) {
            int p = i >> 3, q = i & 7;
            float4 v = *(const float4*)&x[(base + t * 128 + p) * CIN + q * 4];
            *(float2*)&xs[p * 34 + q * 4]     = make_float2(v.x, v.y);
            *(float2*)&xs[p * 34 + q * 4 + 2] = make_float2(v.z, v.w);
        }
        __syncthreads();
        for (int pp = 0; pp < 16; pp++) {
            const float* xr = &xs[(rep * 16 + pp) * 34];
            float xi[4]; u64 xj[4];
#pragma unroll
            for (int a = 0; a < 4; a++) xi[a] = xr[i0 + a];
#pragma unroll
            for (int q = 0; q < 4; q++) xj[q] = *(const u64*)&xr[j0 + 2 * q];
#pragma unroll
            for (int a = 0; a < 4; a++) {
                u64 ap = pk2(xi[a], xi[a]);
#pragma unroll
                for (int q = 0; q < 4; q++) fma2(acc[a][q], ap, xj[q]);
            }
            if ((tt & 3) == 0)
#pragma unroll
                for (int a = 0; a < 4; a++) ssum[a] += xi[a];
        }
    }
#pragma unroll
    for (int a = 0; a < 4; a++)
#pragma unroll
        for (int q = 0; q < 4; q++) {
            float2 f = upk2(acc[a][q]);
            atomicAdd(&g_mom[(i0 + a) * 32 + j0 + 2 * q], f.x);
            atomicAdd(&g_mom[(i0 + a) * 32 + j0 + 2 * q + 1], f.y);
        }
    if ((tt & 3) == 0)
#pragma unroll
        for (int a = 0; a < 4; a++) atomicAdd(&g_mom[1024 + i0 + a], ssum[a]);
}

__global__ __launch_bounds__(256) void k_gemm1f(const float* __restrict__ x,
                                                const float* __restrict__ w1,
                                                const float* __restrict__ b1,
                                                const float* __restrict__ g1,
                                                const float* __restrict__ be1,
                                                float invN, int N) {
    __shared__ __align__(16) float w1s[K1 * CIN];
    __shared__ float cf[3 * K1];
    __shared__ uint32_t sh_hi[256 * 17];
    __shared__ uint32_t sh_lo[256 * 17];
    int tid = threadIdx.x, lane = tid & 31, w = tid >> 5;
    for (int i = tid; i < K1 * CIN; i += 256) w1s[i] = w1[i];
    if (tid < K1) cf[2 * K1 + tid] = b1[tid];
    size_t p0 = (size_t)blockIdx.x * 256;
    u64 xp2[16];
    const float4* xp = (const float4*)(x + (p0 + tid) * CIN);
#pragma unroll
    for (int q = 0; q < 8; q++) {
        float4 v = xp[q];
        xp2[2 * q] = pk2(v.x, v.y); xp2[2 * q + 1] = pk2(v.z, v.w);
    }
    __syncthreads();
    for (int rr = 0; rr < 16; rr++) {
        int k = rr * 8 + w;
        float wl = w1s[k * 32 + lane];
        float col = 0.f;
        for (int i = 0; i < 32; i++)
            col += __shfl_sync(0xffffffffu, wl, i) * g_mom[i * 32 + lane];
        float q2 = wl * col, ml = wl * g_mom[1024 + lane];
#pragma unroll
        for (int o = 16; o; o >>= 1) {
            q2 += __shfl_down_sync(0xffffffffu, q2, o);
            ml += __shfl_down_sync(0xffffffffu, ml, o);
        }
        if (lane == 0) {
            ml *= invN;
            float bk = b1[k], mu = ml + bk;
            float var = q2 * invN + 2.f * bk * ml + bk * bk - mu * mu;
            float a = g1[k] * rsqrtf(var + 1e-5f);
            cf[k] = a;
            cf[K1 + k] = fmaf(-mu, a, be1[k]);
        }
    }
    __syncthreads();
    for (int cc = 0; cc < 4; cc++) {
#pragma unroll 2
        for (int chp = 0; chp < 16; chp++) {
            int ch0 = cc * 32 + chp * 2;
            float an[2];
#pragma unroll
            for (int s = 0; s < 2; s++) {
                int ch = ch0 + s;
                const u64* wr = (const u64*)(w1s + ch * CIN);
                u64 a = 0ull;
#pragma unroll
                for (int q = 0; q < 16; q++) fma2(a, xp2[q], wr[q]);
                float2 f = upk2(a);
                float h = f.x + f.y + cf[2 * K1 + ch];
                an[s] = fmaxf(fmaf(cf[ch], h, cf[K1 + ch]), 0.f);
            }
            __nv_bfloat162 h2 = __floats2bfloat162_rn(an[0], an[1]);
            float r0 = an[0] - __low2float(h2);
            float r1 = an[1] - __high2float(h2);
            __nv_bfloat162 l2 = __floats2bfloat162_rn(r0, r1);
            uint32_t hu, lu; memcpy(&hu, &h2, 4); memcpy(&lu, &l2, 4);
            sh_hi[tid * 17 + chp] = hu;
            sh_lo[tid * 17 + chp] = lu;
        }
        __syncthreads();
        for (int i = tid; i < 1024; i += 256) {
            int pp = i >> 2, q4 = i & 3;
            uint4 vh, vl;
            vh.x = sh_hi[pp * 17 + q4 * 4];     vh.y = sh_hi[pp * 17 + q4 * 4 + 1];
            vh.z = sh_hi[pp * 17 + q4 * 4 + 2]; vh.w = sh_hi[pp * 17 + q4 * 4 + 3];
            vl.x = sh_lo[pp * 17 + q4 * 4];     vl.y = sh_lo[pp * 17 + q4 * 4 + 1];
            vl.z = sh_lo[pp * 17 + q4 * 4 + 2]; vl.w = sh_lo[pp * 17 + q4 * 4 + 3];
            g_Ah4[(p0 + pp) * 16 + cc * 4 + q4] = vh;
            g_Al4[(p0 + pp) * 16 + cc * 4 + q4] = vl;
        }
        __syncthreads();
    }
}

// GEMM2: m64 tile, A resident, B streamed; 2 blocks/SM. (R14-proven)
#define SM_A   0
#define SM_B   40960
#define SM_STG 81920
#define SM_BS  98304
#define SM_TOTAL 100352

__global__ __launch_bounds__(256, 2) void k_gemm2_mma(const float* __restrict__ b2, int N) {
    extern __shared__ char smem[];
    uint32_t sb = smem_u32(smem);
    int tid = threadIdx.x, lane = tid & 31, wid = tid >> 5;
    int wm = wid >> 2, wn = wid & 3;
    size_t p0 = (size_t)blockIdx.x * 64;
    float* bs = (float*)(smem + SM_BS);
    bs[tid] = b2[tid]; bs[256 + tid] = b2[256 + tid];

    for (int e = tid; e < 2048; e += 256) {
        int ck = e >> 9, hl = (e >> 8) & 1, r = (e >> 2) & 63, c2 = e & 3;
        uint32_t dst = sb + (uint32_t)(ck * 10240 + hl * 5120 + r * 80 + c2 * 16);
        const char* base = hl ? (const char*)g_Al4 : (const char*)g_Ah4;
        cpasync16(dst, base + (p0 + r) * 256 + ck * 64 + c2 * 16);
    }
    CP_COMMIT();
    auto copyB = [&](int step, int buf) {
        int nb = step >> 2, ck = step & 3;
        for (int e = tid; e < 1024; e += 256) {
            int hl = e >> 9, r = (e >> 2) & 127, c2 = e & 3;
            uint32_t dst = sb + SM_B + (uint32_t)(buf * 20480 + hl * 10240 + r * 80 + c2 * 16);
            const char* base = hl ? (const char*)g_Bl4 : (const char*)g_Bh4;
            cpasync16(dst, base + (size_t)(nb * 128 + r) * 256 + ck * 64 + c2 * 16);
        }
        CP_COMMIT();
    };
    copyB(0, 0); copyB(1, 1);

    uint32_t laneOff = (uint32_t)((lane & 15) * 80 + (lane >> 4) * 16);
    float* stgf = (float*)(smem + SM_STG);
    int t4 = lane >> 2, t2 = 2 * (lane & 3);
    int col = tid & 127, half = tid >> 7;

    for (int nb = 0; nb < 4; nb++) {
        float acc[2][4][4];
#pragma unroll
        for (int mi = 0; mi < 2; mi++)
#pragma unroll
            for (int c = 0; c < 4; c++)
#pragma unroll
                for (int j = 0; j < 4; j++) acc[mi][c][j] = 0.f;
        for (int ck = 0; ck < 4; ck++) {
            int step = nb * 4 + ck;
            if (step < 15) asm volatile("cp.async.wait_group 1;" ::: "memory");
            else           asm volatile("cp.async.wait_group 0;" ::: "memory");
            __syncthreads();
            uint32_t aB = sb + (uint32_t)(ck * 10240) + (uint32_t)(wm * 32 * 80) + laneOff;
            uint32_t bB = sb + SM_B + (uint32_t)((step & 1) * 20480) + (uint32_t)(wn * 32 * 80) + laneOff;
#pragma unroll
            for (int ksl = 0; ksl < 2; ksl++) {
                uint32_t ah[2][4], al[2][4];
#pragma unroll
                for (int mi = 0; mi < 2; mi++) {
                    ldm4(ah[mi], aB + mi * 1280 + ksl * 32);
                    ldm4(al[mi], aB + 5120 + mi * 1280 + ksl * 32);
                }
#pragma unroll
                for (int nj = 0; nj < 2; nj++) {
                    uint32_t bh[4], bl[4];
                    ldm4(bh, bB + nj * 1280 + ksl * 32);
                    ldm4(bl, bB + 10240 + nj * 1280 + ksl * 32);
#pragma unroll
                    for (int mi = 0; mi < 2; mi++)
#pragma unroll
                        for (int s = 0; s < 2; s++) {
                            float* d = acc[mi][nj * 2 + s];
                            mma16816(d, ah[mi], bh[s], bh[s + 2]);
                            mma16816(d, ah[mi], bl[s], bl[s + 2]);
                            mma16816(d, al[mi], bh[s], bh[s + 2]);
                        }
                }
            }
            __syncthreads();
            if (step + 2 <= 15) copyB(step + 2, step & 1);
        }
        int n0 = nb * 128;
        float sst = 0.f, qst = 0.f;
        float bias = bs[n0 + col];
#pragma unroll
        for (int pass = 0; pass < 2; pass++) {
            if (wm == pass) {
#pragma unroll
                for (int mi = 0; mi < 2; mi++) {
                    int mB = mi * 16 + t4;
#pragma unroll
                    for (int c = 0; c < 4; c++) {
                        int nn = wn * 32 + c * 8 + t2;
                        float* d = acc[mi][c];
                        *(float2*)&stgf[mB * 128 + (nn ^ ((mB & 7) << 2))] = make_float2(d[0], d[1]);
                        int m2 = mB + 8;
                        *(float2*)&stgf[m2 * 128 + (nn ^ ((m2 & 7) << 2))] = make_float2(d[2], d[3]);
                    }
                }
            }
            __syncthreads();
#pragma unroll
            for (int it = 0; it < 4; it++) {
                int task = tid + it * 256;
                int rr = task >> 5, c4 = (task & 31) * 4;
                float4 v = *(const float4*)&stgf[rr * 128 + (c4 ^ ((rr & 7) << 2))];
                float4 bb = *(const float4*)&bs[n0 + c4];
                v.x += bb.x; v.y += bb.y; v.z += bb.z; v.w += bb.w;
                *(float4*)&g_att[(p0 + pass * 32 + rr) * K2 + n0 + c4] = v;
            }
#pragma unroll 4
            for (int r = half * 16; r < half * 16 + 16; r++) {
                float v = stgf[r * 128 + (col ^ ((r & 7) << 2))] + bias;
                sst += v; qst += v * v;
            }
            __syncthreads();
        }
        atomicAdd(&g_s2[n0 + col], sst);
        atomicAdd(&g_s2[K2 + n0 + col], qst);
    }
}

// pool via HMMA; BN2 coefs inline; ZSPL z-splits, coefs hoisted to registers
#define PRAW 0
#define PIMG 65536
#define PIMX 100352
#define PBN  110592
#define PSM_TOTAL 111616

__global__ __launch_bounds__(256, 2) void k_pool_mma(const float* __restrict__ x,
                                                     float* __restrict__ gp_out,
                                                     const float* __restrict__ g2,
                                                     const float* __restrict__ be2,
                                                     float invN, int L) {
    extern __shared__ char smem[];
    uint32_t sb = smem_u32(smem);
    int tid = threadIdx.x, lane = tid & 31, wid = tid >> 5;
    int wm = wid >> 1, wn = wid & 1;
    int b = blockIdx.x, kg = blockIdx.y, z = blockIdx.z;
    int k0 = kg * 128;
    int lsl = L / ZSPL;
    size_t pbase = (size_t)b * L + (size_t)z * lsl;
    float* a2s = (float*)(smem + PBN);
    float* c2s = a2s + 128;
    if (tid < 128) {
        int k = k0 + tid;
        float mu = g_s2[k] * invN;
        float var = g_s2[K2 + k] * invN - mu * mu;
        float a = g2[k] * rsqrtf(var + 1e-5f);
        a2s[tid] = a;
        c2s[tid] = fmaf(-mu, a, be2[k]);
    }

    int kq = tid & 31;
    float gpl[4] = {0.f, 0.f, 0.f, 0.f};
    float acc[2][2][4];
#pragma unroll
    for (int mi = 0; mi < 2; mi++)
#pragma unroll
        for (int nj = 0; nj < 2; nj++)
#pragma unroll
            for (int j = 0; j < 4; j++) acc[mi][nj][j] = 0.f;

    int trow = (lane & 7) + ((lane >> 4) << 3);
    int tcol = (lane >> 3) & 1;
    int nchunks = lsl >> 6;

    auto loadraw = [&](int ch, int buf) {
        size_t row0 = pbase + (size_t)ch * 64;
        for (int e = tid; e < 2048; e += 256) {
            int p = e >> 5, c16 = e & 31;
            cpasync16(sb + PRAW + (uint32_t)(buf * 32768 + p * 512 + c16 * 16),
                      (const char*)&g_att[(row0 + p) * K2 + k0] + c16 * 16);
        }
        CP_COMMIT();
    };
    loadraw(0, 0);
    __syncthreads();
    // hoist this thread's 4 coef pairs to registers
    float ca[4], cc[4];
#pragma unroll
    for (int j = 0; j < 4; j++) { ca[j] = a2s[kq * 4 + j]; cc[j] = c2s[kq * 4 + j]; }

    for (int ch = 0; ch < nchunks; ch++) {
        int buf = ch & 1;
        asm volatile("cp.async.wait_group 0;" ::: "memory");
        __syncthreads();
        if (ch + 1 < nchunks) loadraw(ch + 1, buf ^ 1);
        const float* raw = (const float*)(smem + PRAW + buf * 32768);
        for (int i = tid; i < 2048; i += 256) {
            int p = i >> 5;
            float4 v = *(const float4*)(raw + p * 128 + kq * 4);
            float f0 = fmaxf(fmaf(ca[0], v.x, cc[0]), 0.f);
            float f1 = fmaxf(fmaf(ca[1], v.y, cc[1]), 0.f);
            float f2 = fmaxf(fmaf(ca[2], v.z, cc[2]), 0.f);
            float f3 = fmaxf(fmaf(ca[3], v.w, cc[3]), 0.f);
            gpl[0] += f0; gpl[1] += f1; gpl[2] += f2; gpl[3] += f3;
            __nv_bfloat162 h01 = __floats2bfloat162_rn(f0, f1);
            __nv_bfloat162 h23 = __floats2bfloat162_rn(f2, f3);
            __nv_bfloat162 l01 = __floats2bfloat162_rn(f0 - __low2float(h01), f1 - __high2float(h01));
            __nv_bfloat162 l23 = __floats2bfloat162_rn(f2 - __low2float(h23), f3 - __high2float(h23));
            uint2 hv, lv;
            memcpy(&hv.x, &h01, 4); memcpy(&hv.y, &h23, 4);
            memcpy(&lv.x, &l01, 4); memcpy(&lv.y, &l23, 4);
            *(uint2*)(smem + PIMG + p * 272 + kq * 8) = hv;
            *(uint2*)(smem + PIMG + 17408 + p * 272 + kq * 8) = lv;
        }
        for (int i = tid; i < 512; i += 256) {
            int p = i >> 3, cq = i & 7;
            float4 v = *(const float4*)&x[(pbase + (size_t)ch * 64 + p) * CIN + cq * 4];
            __nv_bfloat162 h01 = __floats2bfloat162_rn(v.x, v.y);
            __nv_bfloat162 h23 = __floats2bfloat162_rn(v.z, v.w);
            __nv_bfloat162 l01 = __floats2bfloat162_rn(v.x - __low2float(h01), v.y - __high2float(h01));
            __nv_bfloat162 l23 = __floats2bfloat162_rn(v.z - __low2float(h23), v.w - __high2float(h23));
            uint2 hv, lv;
            memcpy(&hv.x, &h01, 4); memcpy(&hv.y, &h23, 4);
            memcpy(&lv.x, &l01, 4); memcpy(&lv.y, &l23, 4);
            *(uint2*)(smem + PIMX + p * 80 + cq * 8) = hv;
            *(uint2*)(smem + PIMX + 5120 + p * 80 + cq * 8) = lv;
        }
        __syncthreads();
#pragma unroll
        for (int ps = 0; ps < 4; ps++) {
            uint32_t arow = sb + PIMG + (uint32_t)((ps * 16 + trow) * 272 + tcol * 16);
            uint32_t xrow = sb + PIMX + (uint32_t)((ps * 16 + trow) * 80 + wn * 32 + tcol * 16);
            uint32_t ah[2][4], al[2][4];
#pragma unroll
            for (int mi = 0; mi < 2; mi++) {
                uint32_t kb = (uint32_t)((wm * 32 + mi * 16) * 2);
                ldm4t(ah[mi], arow + kb);
                ldm4t(al[mi], arow + 17408 + kb);
            }
            uint32_t xh[4], xl[4];
            ldm4t(xh, xrow);
            ldm4t(xl, xrow + 5120);
#pragma unroll
            for (int mi = 0; mi < 2; mi++)
#pragma unroll
                for (int nj = 0; nj < 2; nj++) {
                    float* d = acc[mi][nj];
                    mma16816(d, ah[mi], xh[nj], xh[nj + 2]);
                    mma16816(d, ah[mi], xl[nj], xl[nj + 2]);
                    mma16816(d, al[mi], xh[nj], xh[nj + 2]);
                }
        }
    }
    int g = lane >> 2, t2 = 2 * (lane & 3);
#pragma unroll
    for (int mi = 0; mi < 2; mi++) {
        int kch = k0 + wm * 32 + mi * 16 + g;
#pragma unroll
        for (int nj = 0; nj < 2; nj++) {
            int c = wn * 16 + nj * 8 + t2;
            float* d = acc[mi][nj];
            atomicAdd(&g_pooled[((size_t)b * K2 + kch) * CIN + c], d[0]);
            atomicAdd(&g_pooled[((size_t)b * K2 + kch) * CIN + c + 1], d[1]);
            atomicAdd(&g_pooled[((size_t)b * K2 + kch + 8) * CIN + c], d[2]);
            atomicAdd(&g_pooled[((size_t)b * K2 + kch + 8) * CIN + c + 1], d[3]);
        }
    }
#pragma unroll
    for (int j = 0; j < 4; j++)
        atomicAdd(&gp_out[b * K2 + k0 + kq * 4 + j], gpl[j]);
}

__global__ __launch_bounds__(256) void k_fc(const float* __restrict__ wf,
                                            const float* __restrict__ bf,
                                            int B, float invL) {
    int j = blockIdx.x, tid = threadIdx.x;
    const float* wrow = wf + (size_t)j * (K2 * CIN);
    float acc[MAXB];
#pragma unroll
    for (int b = 0; b < MAXB; b++) acc[b] = 0.f;
    for (int i = tid; i < K2 * CIN; i += 256) {
        float w = wrow[i];
#pragma unroll
        for (int b = 0; b < MAXB; b++)
            if (b < B) acc[b] += w * g_pooled[(size_t)b * (K2 * CIN) + i];
    }
    __shared__ float red[8][MAXB];
    int lane = tid & 31, w = tid >> 5;
#pragma unroll
    for (int b = 0; b < MAXB; b++) {
        float v = acc[b];
#pragma unroll
        for (int o = 16; o; o >>= 1) v += __shfl_down_sync(0xffffffffu, v, o);
        if (lane == 0) red[w][b] = v;
    }
    __syncthreads();
    if (tid < B) {
        float ssum = 0.f;
        for (int i = 0; i < 8; i++) ssum += red[i][tid];
        g_resraw[tid * FCD + j] = fmaf(ssum, invL, bf[j]);
    }
}

__global__ void k_final(float* __restrict__ outp, const float* __restrict__ gf,
                        const float* __restrict__ bef, int B, int L) {
    int j = threadIdx.x;
    __shared__ float rows[MAXB];
    if (j < B) rows[j] = 0.f;
    __syncthreads();
    float v[MAXB];
    float s = 0.f, q = 0.f;
    for (int b = 0; b < B; b++) {
        v[b] = g_resraw[b * FCD + j];
        s += v[b]; q += v[b] * v[b];
    }
    float invB = 1.f / (float)B;
    float mu = s * invB;
    float var = q * invB - mu * mu;
    float a = gf[j] * rsqrtf(var + 1e-5f);
    float c = fmaf(-mu, a, bef[j]);
    for (int b = 0; b < B; b++) {
        v[b] = fmaf(a, v[b], c);
        atomicAdd(&rows[b], v[b] * v[b]);
    }
    __syncthreads();
    for (int b = 0; b < B; b++)
        outp[b * FCD + j] = v[b] / fmaxf(sqrtf(rows[b]), 1e-12f);
    if (j < B) outp[B * FCD + B * K2 + j] = (float)L;
}

extern "C" void kernel_launch(void* const* d_in, const int* in_sizes, int n_in,
                              void* d_out, int out_size) {
    const float* x   = (const float*)d_in[0];
    const float* w1  = (const float*)d_in[1];
    const float* b1  = (const float*)d_in[2];
    const float* g1  = (const float*)d_in[3];
    const float* be1 = (const float*)d_in[4];
    const float* w2  = (const float*)d_in[5];
    const float* b2  = (const float*)d_in[6];
    const float* g2  = (const float*)d_in[7];
    const float* be2 = (const float*)d_in[8];
    const float* wf  = (const float*)d_in[9];
    const float* bf  = (const float*)d_in[10];
    const float* gf  = (const float*)d_in[11];
    const float* bef = (const float*)d_in[12];
    float* outp = (float*)d_out;

    int N = in_sizes[0] / CIN;
    int B = out_size / (FCD + K2 + 1);
    int L = N / B;
    float invN = 1.f / (float)N;
    float invL = 1.f / (float)L;

    cudaFuncSetAttribute(k_gemm2_mma, cudaFuncAttributeMaxDynamicSharedMemorySize, SM_TOTAL);
    cudaFuncSetAttribute(k_pool_mma, cudaFuncAttributeMaxDynamicSharedMemorySize, PSM_TOTAL);

    k_zero<<<(B * K2 * CIN + 255) / 256, 256>>>(outp, B, w2);
    k_moments<<<N / 8192, 256>>>(x, N);
    k_gemm1f<<<N / 256, 256>>>(x, w1, b1, g1, be1, invN, N);
    k_gemm2_mma<<<N / 64, 256, SM_TOTAL>>>(b2, N);
    k_pool_mma<<<dim3(B, K2 / 128, ZSPL), 256, PSM_TOTAL>>>(x, outp + B * FCD, g2, be2, invN, L);
    k_fc<<<FCD, 256>>>(wf, bf, B, invL);
    k_final<<<1, FCD>>>(outp, gf, bef, B, L);
}